// round 1
// baseline (speedup 1.0000x reference)
#include <cuda_runtime.h>

#define D_IN  2048
#define H1    128
#define H2    64
#define F1    32
#define BATCH 64
#define TSEQ  512
#define MTOT  (BATCH * TSEQ)   // 32768

// Scratch for xp1 = x @ W_ih1^T + b_ih1  (16 MB, static device global: allocation-free)
__device__ float g_xp1[MTOT * H1];

// ---------------- packed f32x2 helpers (Blackwell FFMA2, PTX-only path) ----------------
__device__ __forceinline__ void fma2(unsigned long long &acc, unsigned long long a, unsigned long long b) {
    asm("fma.rn.f32x2 %0, %1, %2, %0;" : "+l"(acc) : "l"(a), "l"(b));
}
__device__ __forceinline__ unsigned long long pack2(float x) {
    unsigned long long d;
    unsigned u = __float_as_uint(x);
    asm("mov.b64 %0, {%1, %1};" : "=l"(d) : "r"(u));
    return d;
}
__device__ __forceinline__ float lo32(unsigned long long v) { return __uint_as_float((unsigned)v); }
__device__ __forceinline__ float hi32(unsigned long long v) { return __uint_as_float((unsigned)(v >> 32)); }

// =====================================================================================
// Kernel 1: xp1[m, n] = sum_k x[m, k] * W_ih1[n, k] + b_ih1[n]
// M = 32768, N = 128, K = 2048.  BM=128, BN=128(all), BK=16. 256 threads, 8x8 micro-tile
// via packed f32x2 FMAs (acc as 8x4 u64). Register-staged double buffering.
// =====================================================================================
__global__ void __launch_bounds__(256, 1) gemm_xp1_kernel(
    const float* __restrict__ X, const float* __restrict__ W, const float* __restrict__ bias)
{
    // transposed tiles [k][m]/[k][n] with pad 132 (STS conflict relief + 16B-aligned rows)
    __shared__ __align__(16) float As[16 * 132];
    __shared__ __align__(16) float Bs[16 * 132];

    const int tid = threadIdx.x;
    const int tx = tid & 15, ty = tid >> 4;
    const int mBase = blockIdx.x * 128;

    // load mapping: each thread stages 2 float4 per tile per matrix
    const int ar0 = tid >> 2;            // 0..63
    const int ac0 = (tid & 3) * 4;       // k-offset within BK: 0,4,8,12
    const int ar1 = ar0 + 64;            // 64..127

    const float* Ap0 = X + (size_t)(mBase + ar0) * D_IN + ac0;
    const float* Ap1 = X + (size_t)(mBase + ar1) * D_IN + ac0;
    const float* Bp0 = W + (size_t)ar0 * D_IN + ac0;
    const float* Bp1 = W + (size_t)ar1 * D_IN + ac0;

    float4 ra0 = *(const float4*)Ap0;
    float4 ra1 = *(const float4*)Ap1;
    float4 rb0 = *(const float4*)Bp0;
    float4 rb1 = *(const float4*)Bp1;

    unsigned long long acc[8][4];
#pragma unroll
    for (int r = 0; r < 8; ++r)
#pragma unroll
        for (int c = 0; c < 4; ++c) acc[r][c] = 0ull;

    for (int it = 0; it < 128; ++it) {
        // store staged tile (tile `it`) to smem, transposed
        As[(ac0 + 0) * 132 + ar0] = ra0.x;
        As[(ac0 + 1) * 132 + ar0] = ra0.y;
        As[(ac0 + 2) * 132 + ar0] = ra0.z;
        As[(ac0 + 3) * 132 + ar0] = ra0.w;
        As[(ac0 + 0) * 132 + ar1] = ra1.x;
        As[(ac0 + 1) * 132 + ar1] = ra1.y;
        As[(ac0 + 2) * 132 + ar1] = ra1.z;
        As[(ac0 + 3) * 132 + ar1] = ra1.w;
        Bs[(ac0 + 0) * 132 + ar0] = rb0.x;
        Bs[(ac0 + 1) * 132 + ar0] = rb0.y;
        Bs[(ac0 + 2) * 132 + ar0] = rb0.z;
        Bs[(ac0 + 3) * 132 + ar0] = rb0.w;
        Bs[(ac0 + 0) * 132 + ar1] = rb1.x;
        Bs[(ac0 + 1) * 132 + ar1] = rb1.y;
        Bs[(ac0 + 2) * 132 + ar1] = rb1.z;
        Bs[(ac0 + 3) * 132 + ar1] = rb1.w;
        __syncthreads();

        // prefetch next tile into registers (latency hidden by ~1k-cycle compute below)
        if (it < 127) {
            const int ko = (it + 1) * 16;
            ra0 = *(const float4*)(Ap0 + ko);
            ra1 = *(const float4*)(Ap1 + ko);
            rb0 = *(const float4*)(Bp0 + ko);
            rb1 = *(const float4*)(Bp1 + ko);
        }

#pragma unroll
        for (int kk = 0; kk < 16; ++kk) {
            const float* asr = As + kk * 132;
            const float* bsr = Bs + kk * 132;
            float4 a0 = *(const float4*)(asr + ty * 4);
            float4 a1 = *(const float4*)(asr + 64 + ty * 4);
            ulonglong2 b0 = *(const ulonglong2*)(bsr + tx * 4);
            ulonglong2 b1 = *(const ulonglong2*)(bsr + 64 + tx * 4);
            float av[8] = {a0.x, a0.y, a0.z, a0.w, a1.x, a1.y, a1.z, a1.w};
            unsigned long long bv[4] = {b0.x, b0.y, b1.x, b1.y};
#pragma unroll
            for (int r = 0; r < 8; ++r) {
                unsigned long long pa = pack2(av[r]);
#pragma unroll
                for (int c = 0; c < 4; ++c) fma2(acc[r][c], pa, bv[c]);
            }
        }
        __syncthreads();
    }

    // epilogue: add bias, write fp32 xp1
    float2 bp[4];
    bp[0] = *(const float2*)(bias + tx * 4);
    bp[1] = *(const float2*)(bias + tx * 4 + 2);
    bp[2] = *(const float2*)(bias + 64 + tx * 4);
    bp[3] = *(const float2*)(bias + 64 + tx * 4 + 2);

#pragma unroll
    for (int rr = 0; rr < 8; ++rr) {
        int row = mBase + ((rr < 4) ? (ty * 4 + rr) : (64 + ty * 4 + rr - 4));
        float* op = g_xp1 + (size_t)row * H1;
#pragma unroll
        for (int c = 0; c < 4; ++c) {
            int col = (c < 2) ? (tx * 4 + c * 2) : (64 + tx * 4 + (c - 2) * 2);
            float2 o;
            o.x = lo32(acc[rr][c]) + bp[c].x;
            o.y = hi32(acc[rr][c]) + bp[c].y;
            *(float2*)(op + col) = o;
        }
    }
}

// =====================================================================================
// Kernel 2: fused dual-RNN scan + FC head. One CTA per batch element, 256 threads.
// Weights register-resident. h double-buffered in smem -> ONE __syncthreads per step.
//   layer1: thread pair (2i,2i+1) computes h1[i]  (64 MACs each, shfl-xor-1 reduce)
//   layer2: thread quad computes h2[j]            (32+16 MACs each, shfl-xor-1,2 reduce)
// =====================================================================================
__global__ void __launch_bounds__(256, 1) rnn_scan_kernel(
    const float* __restrict__ W_hh1, const float* __restrict__ b_hh1,
    const float* __restrict__ W_ih2, const float* __restrict__ W_hh2,
    const float* __restrict__ b_ih2, const float* __restrict__ b_hh2,
    const float* __restrict__ W_fc1, const float* __restrict__ b_fc1,
    const float* __restrict__ W_fc2, const float* __restrict__ b_fc2,
    float* __restrict__ out)
{
    __shared__ __align__(16) float h1s[2][H1];
    __shared__ __align__(16) float h2s[2][H2];

    const int tid = threadIdx.x;
    const int bb = blockIdx.x;
    const int i1 = tid >> 1, half = tid & 1;
    const int j2 = tid >> 2, q = tid & 3;

    // register-resident weight slices
    float w1[64];
#pragma unroll
    for (int k = 0; k < 64; ++k) w1[k] = W_hh1[i1 * H1 + half * 64 + k];
    float w2i[32];
#pragma unroll
    for (int k = 0; k < 32; ++k) w2i[k] = W_ih2[j2 * H1 + q * 32 + k];
    float w2h[16];
#pragma unroll
    for (int k = 0; k < 16; ++k) w2h[k] = W_hh2[j2 * H2 + q * 16 + k];

    const float bias1 = b_hh1[i1];
    const float bias2 = b_ih2[j2] + b_hh2[j2];

    if (tid < H1) h1s[0][tid] = 0.f;
    if (tid < H2) h2s[0][tid] = 0.f;
    __syncthreads();

    const float* xp = g_xp1 + (size_t)bb * TSEQ * H1;

    for (int t = 0; t < TSEQ; ++t) {
        const int p = t & 1;

        float xv = 0.f;
        if (!half) xv = __ldg(xp + t * H1 + i1);   // issued early; hidden by dot below

        // ---- layer 1: acc = dot(W_hh1[i1, half*64 : half*64+64], h1_old) ----
        const float* hb = &h1s[p][half * 64];
        float a0 = 0.f, a1 = 0.f, a2 = 0.f, a3 = 0.f;
#pragma unroll
        for (int k4 = 0; k4 < 16; ++k4) {
            float4 h = *(const float4*)(hb + k4 * 4);
            a0 = fmaf(w1[k4 * 4 + 0], h.x, a0);
            a1 = fmaf(w1[k4 * 4 + 1], h.y, a1);
            a2 = fmaf(w1[k4 * 4 + 2], h.z, a2);
            a3 = fmaf(w1[k4 * 4 + 3], h.w, a3);
        }
        float acc = (a0 + a1) + (a2 + a3);
        acc += __shfl_xor_sync(0xffffffffu, acc, 1);
        if (!half) h1s[p ^ 1][i1] = tanhf(xv + acc + bias1);
        __syncthreads();   // single barrier per step (double-buffered h)

        // ---- layer 2: W_ih2 @ h1_new + W_hh2 @ h2_old ----
        const float* h1n = &h1s[p ^ 1][q * 32];
        const float* h2o = &h2s[p][q * 16];
        float c0 = 0.f, c1 = 0.f, c2 = 0.f, c3 = 0.f;
#pragma unroll
        for (int k4 = 0; k4 < 8; ++k4) {
            float4 h = *(const float4*)(h1n + k4 * 4);
            c0 = fmaf(w2i[k4 * 4 + 0], h.x, c0);
            c1 = fmaf(w2i[k4 * 4 + 1], h.y, c1);
            c2 = fmaf(w2i[k4 * 4 + 2], h.z, c2);
            c3 = fmaf(w2i[k4 * 4 + 3], h.w, c3);
        }
#pragma unroll
        for (int k4 = 0; k4 < 4; ++k4) {
            float4 h = *(const float4*)(h2o + k4 * 4);
            c0 = fmaf(w2h[k4 * 4 + 0], h.x, c0);
            c1 = fmaf(w2h[k4 * 4 + 1], h.y, c1);
            c2 = fmaf(w2h[k4 * 4 + 2], h.z, c2);
            c3 = fmaf(w2h[k4 * 4 + 3], h.w, c3);
        }
        float acc2 = (c0 + c1) + (c2 + c3);
        acc2 += __shfl_xor_sync(0xffffffffu, acc2, 1);
        acc2 += __shfl_xor_sync(0xffffffffu, acc2, 2);
        if (q == 0) h2s[p ^ 1][j2] = tanhf(acc2 + bias2);
        // no trailing barrier: next iteration's barrier provides all needed ordering
    }
    __syncthreads();   // make final h2 (in h2s[0], since TSEQ even) visible

    // ---- FC head: out[bb] = W_fc2 @ relu(W_fc1 @ h_last + b_fc1) + b_fc2 ----
    if (tid < F1) {
        const float* hf = h2s[0];
        float acc = b_fc1[tid];
#pragma unroll
        for (int k = 0; k < H2; ++k) acc = fmaf(W_fc1[tid * H2 + k], hf[k], acc);
        float r = fmaxf(acc, 0.f) * W_fc2[tid];
#pragma unroll
        for (int s = 16; s > 0; s >>= 1) r += __shfl_xor_sync(0xffffffffu, r, s);
        if (tid == 0) out[bb] = r + b_fc2[0];
    }
}

// =====================================================================================
extern "C" void kernel_launch(void* const* d_in, const int* in_sizes, int n_in,
                              void* d_out, int out_size)
{
    const float* x     = (const float*)d_in[0];
    const float* W_ih1 = (const float*)d_in[1];
    const float* W_hh1 = (const float*)d_in[2];
    const float* b_ih1 = (const float*)d_in[3];
    const float* b_hh1 = (const float*)d_in[4];
    const float* W_ih2 = (const float*)d_in[5];
    const float* W_hh2 = (const float*)d_in[6];
    const float* b_ih2 = (const float*)d_in[7];
    const float* b_hh2 = (const float*)d_in[8];
    const float* W_fc1 = (const float*)d_in[9];
    const float* b_fc1 = (const float*)d_in[10];
    const float* W_fc2 = (const float*)d_in[11];
    const float* b_fc2 = (const float*)d_in[12];
    float* out = (float*)d_out;

    gemm_xp1_kernel<<<MTOT / 128, 256>>>(x, W_ih1, b_ih1);
    rnn_scan_kernel<<<BATCH, 256>>>(W_hh1, b_hh1, W_ih2, W_hh2, b_ih2, b_hh2,
                                    W_fc1, b_fc1, W_fc2, b_fc2, out);
}

// round 2
// speedup vs baseline: 1.6340x; 1.6340x over previous
#include <cuda_runtime.h>

#define D_IN  2048
#define H1    128
#define H2    64
#define F1    32
#define BATCH 64
#define TSEQ  512
#define MTOT  (BATCH * TSEQ)   // 32768

typedef unsigned long long ull;

// Scratch for xp1 = x @ W_ih1^T + b_ih1  (16 MB, static device global: allocation-free)
__device__ float g_xp1[MTOT * H1];

// ---------------- packed f32x2 helpers (Blackwell FFMA2, PTX-only path) ----------------
__device__ __forceinline__ void fma2(ull &acc, ull a, ull b) {
    asm("fma.rn.f32x2 %0, %1, %2, %0;" : "+l"(acc) : "l"(a), "l"(b));
}
__device__ __forceinline__ void add2(ull &d, ull a, ull b) {
    asm("add.rn.f32x2 %0, %1, %2;" : "=l"(d) : "l"(a), "l"(b));
}
__device__ __forceinline__ ull pack2(float x) {
    ull d;
    unsigned u = __float_as_uint(x);
    asm("mov.b64 %0, {%1, %1};" : "=l"(d) : "r"(u));
    return d;
}
__device__ __forceinline__ float lo32(ull v) { return __uint_as_float((unsigned)v); }
__device__ __forceinline__ float hi32(ull v) { return __uint_as_float((unsigned)(v >> 32)); }

// fast, accurate tanh: 1 - 2/(e^{2x}+1).  MUFU.EX2 + MUFU.RCP, rel err ~1e-6.
// e=inf -> 1 exactly; e->0 -> -1 exactly.
__device__ __forceinline__ float fast_tanh(float x) {
    float e = __expf(2.0f * x);
    return 1.0f - __fdividef(2.0f, e + 1.0f);
}

// named-barrier helpers
#define BAR_SYNC(id, n)   asm volatile("bar.sync %0, %1;"   :: "r"(id), "r"(n) : "memory")
#define BAR_ARRIVE(id, n) asm volatile("bar.arrive %0, %1;" :: "r"(id), "r"(n) : "memory")

// =====================================================================================
// Kernel 1: xp1[m, n] = sum_k x[m, k] * W_ih1[n, k] + b_ih1[n]   (unchanged from R1)
// =====================================================================================
__global__ void __launch_bounds__(256, 1) gemm_xp1_kernel(
    const float* __restrict__ X, const float* __restrict__ W, const float* __restrict__ bias)
{
    __shared__ __align__(16) float As[16 * 132];
    __shared__ __align__(16) float Bs[16 * 132];

    const int tid = threadIdx.x;
    const int tx = tid & 15, ty = tid >> 4;
    const int mBase = blockIdx.x * 128;

    const int ar0 = tid >> 2;
    const int ac0 = (tid & 3) * 4;
    const int ar1 = ar0 + 64;

    const float* Ap0 = X + (size_t)(mBase + ar0) * D_IN + ac0;
    const float* Ap1 = X + (size_t)(mBase + ar1) * D_IN + ac0;
    const float* Bp0 = W + (size_t)ar0 * D_IN + ac0;
    const float* Bp1 = W + (size_t)ar1 * D_IN + ac0;

    float4 ra0 = *(const float4*)Ap0;
    float4 ra1 = *(const float4*)Ap1;
    float4 rb0 = *(const float4*)Bp0;
    float4 rb1 = *(const float4*)Bp1;

    ull acc[8][4];
#pragma unroll
    for (int r = 0; r < 8; ++r)
#pragma unroll
        for (int c = 0; c < 4; ++c) acc[r][c] = 0ull;

    for (int it = 0; it < 128; ++it) {
        As[(ac0 + 0) * 132 + ar0] = ra0.x;
        As[(ac0 + 1) * 132 + ar0] = ra0.y;
        As[(ac0 + 2) * 132 + ar0] = ra0.z;
        As[(ac0 + 3) * 132 + ar0] = ra0.w;
        As[(ac0 + 0) * 132 + ar1] = ra1.x;
        As[(ac0 + 1) * 132 + ar1] = ra1.y;
        As[(ac0 + 2) * 132 + ar1] = ra1.z;
        As[(ac0 + 3) * 132 + ar1] = ra1.w;
        Bs[(ac0 + 0) * 132 + ar0] = rb0.x;
        Bs[(ac0 + 1) * 132 + ar0] = rb0.y;
        Bs[(ac0 + 2) * 132 + ar0] = rb0.z;
        Bs[(ac0 + 3) * 132 + ar0] = rb0.w;
        Bs[(ac0 + 0) * 132 + ar1] = rb1.x;
        Bs[(ac0 + 1) * 132 + ar1] = rb1.y;
        Bs[(ac0 + 2) * 132 + ar1] = rb1.z;
        Bs[(ac0 + 3) * 132 + ar1] = rb1.w;
        __syncthreads();

        if (it < 127) {
            const int ko = (it + 1) * 16;
            ra0 = *(const float4*)(Ap0 + ko);
            ra1 = *(const float4*)(Ap1 + ko);
            rb0 = *(const float4*)(Bp0 + ko);
            rb1 = *(const float4*)(Bp1 + ko);
        }

#pragma unroll
        for (int kk = 0; kk < 16; ++kk) {
            const float* asr = As + kk * 132;
            const float* bsr = Bs + kk * 132;
            float4 a0 = *(const float4*)(asr + ty * 4);
            float4 a1 = *(const float4*)(asr + 64 + ty * 4);
            ulonglong2 b0 = *(const ulonglong2*)(bsr + tx * 4);
            ulonglong2 b1 = *(const ulonglong2*)(bsr + 64 + tx * 4);
            float av[8] = {a0.x, a0.y, a0.z, a0.w, a1.x, a1.y, a1.z, a1.w};
            ull bv[4] = {b0.x, b0.y, b1.x, b1.y};
#pragma unroll
            for (int r = 0; r < 8; ++r) {
                ull pa = pack2(av[r]);
#pragma unroll
                for (int c = 0; c < 4; ++c) fma2(acc[r][c], pa, bv[c]);
            }
        }
        __syncthreads();
    }

    float2 bp[4];
    bp[0] = *(const float2*)(bias + tx * 4);
    bp[1] = *(const float2*)(bias + tx * 4 + 2);
    bp[2] = *(const float2*)(bias + 64 + tx * 4);
    bp[3] = *(const float2*)(bias + 64 + tx * 4 + 2);

#pragma unroll
    for (int rr = 0; rr < 8; ++rr) {
        int row = mBase + ((rr < 4) ? (ty * 4 + rr) : (64 + ty * 4 + rr - 4));
        float* op = g_xp1 + (size_t)row * H1;
#pragma unroll
        for (int c = 0; c < 4; ++c) {
            int col = (c < 2) ? (tx * 4 + c * 2) : (64 + tx * 4 + (c - 2) * 2);
            float2 o;
            o.x = lo32(acc[rr][c]) + bp[c].x;
            o.y = hi32(acc[rr][c]) + bp[c].y;
            *(float2*)(op + col) = o;
        }
    }
}

// =====================================================================================
// Kernel 2: warp-specialized, software-pipelined dual-RNN scan + FC head.
// One CTA per batch element, 256 threads.
//   Warps 0-3 (threads 0-127):  layer 1.  Thread i computes h1[i] (128-MAC dot, f32x2).
//   Warps 4-7 (threads 128-255): layer 2, ONE STEP BEHIND layer 1. Thread pair (j,half)
//     computes h2[j] (64+32 MACs each, f32x2, shfl-xor-1 reduce).
// h1 double-buffered; producer/consumer handoff via named full/empty barriers:
//   FULL[s]=1+s, EMPTY[s]=3+s (count 256); L1-internal=5, L2-internal=6 (count 128).
// =====================================================================================
__global__ void __launch_bounds__(256, 1) rnn_scan_kernel(
    const float* __restrict__ W_hh1, const float* __restrict__ b_hh1,
    const float* __restrict__ W_ih2, const float* __restrict__ W_hh2,
    const float* __restrict__ b_ih2, const float* __restrict__ b_hh2,
    const float* __restrict__ W_fc1, const float* __restrict__ b_fc1,
    const float* __restrict__ W_fc2, const float* __restrict__ b_fc2,
    float* __restrict__ out)
{
    __shared__ __align__(16) float h1buf[2][H1];
    __shared__ __align__(16) float h2buf[2][H2];

    const int tid = threadIdx.x;
    const int bb = blockIdx.x;

    if (tid < H1) h1buf[1][tid] = 0.f;   // h1(-1) = 0, read at t=0 (s^1 = 1)
    if (tid < H2) h2buf[1][tid] = 0.f;   // h2(-1) = 0

    if (tid < 128) {
        // ---------------- LAYER 1 GROUP ----------------
        const int i = tid;

        ull w1p[64];                      // W_hh1 row i, packed pairs (128 regs)
#pragma unroll
        for (int k = 0; k < 64; ++k)
            w1p[k] = *(const ull*)(W_hh1 + i * H1 + 2 * k);
        const float bias = b_hh1[i];

        const float* xp = g_xp1 + (size_t)bb * TSEQ * H1;
        float xv = __ldg(xp + i);        // xp1(t=0)

        __syncthreads();                 // init visibility

        for (int t = 0; t < TSEQ; ++t) {
            const int s = t & 1;
            if (t >= 2) BAR_SYNC(3 + s, 256);          // EMPTY[s]: L2 done with h1buf[s]

            float xnext = 0.f;
            if (t < TSEQ - 1) xnext = __ldg(xp + (t + 1) * H1 + i);  // prefetch

            const ulonglong2* hp = (const ulonglong2*)h1buf[s ^ 1];
            ull a0 = 0, a1 = 0, a2 = 0, a3 = 0;
#pragma unroll
            for (int k = 0; k < 16; ++k) {
                ulonglong2 h01 = hp[2 * k];
                ulonglong2 h23 = hp[2 * k + 1];
                fma2(a0, w1p[4 * k + 0], h01.x);
                fma2(a1, w1p[4 * k + 1], h01.y);
                fma2(a2, w1p[4 * k + 2], h23.x);
                fma2(a3, w1p[4 * k + 3], h23.y);
            }
            ull s01, s23, sall;
            add2(s01, a0, a1);
            add2(s23, a2, a3);
            add2(sall, s01, s23);
            float dot = lo32(sall) + hi32(sall);

            h1buf[s][i] = fast_tanh(xv + bias + dot);
            BAR_ARRIVE(1 + s, 256);                    // FULL[s]: h1(t) ready for L2
            BAR_SYNC(5, 128);                          // L1 internal: writes visible next step
            xv = xnext;
        }
    } else {
        // ---------------- LAYER 2 GROUP ----------------
        const int u = tid - 128;
        const int j = u >> 1, half = u & 1;

        ull wip[32];                      // W_ih2[j, half*64 .. +64)
#pragma unroll
        for (int k = 0; k < 32; ++k)
            wip[k] = *(const ull*)(W_ih2 + j * H1 + half * 64 + 2 * k);
        ull whp[16];                      // W_hh2[j, half*32 .. +32)
#pragma unroll
        for (int k = 0; k < 16; ++k)
            whp[k] = *(const ull*)(W_hh2 + j * H2 + half * 32 + 2 * k);
        const float bias2 = b_ih2[j] + b_hh2[j];

        __syncthreads();                 // init visibility

        for (int t = 0; t < TSEQ; ++t) {
            const int s = t & 1;
            BAR_SYNC(1 + s, 256);                      // FULL[s]: h1(t) ready

            const ulonglong2* hp = (const ulonglong2*)(h1buf[s] + half * 64);
            ull a0 = 0, a1 = 0, a2 = 0, a3 = 0;
#pragma unroll
            for (int k = 0; k < 8; ++k) {
                ulonglong2 h01 = hp[2 * k];
                ulonglong2 h23 = hp[2 * k + 1];
                fma2(a0, wip[4 * k + 0], h01.x);
                fma2(a1, wip[4 * k + 1], h01.y);
                fma2(a2, wip[4 * k + 2], h23.x);
                fma2(a3, wip[4 * k + 3], h23.y);
            }
            const ulonglong2* gp = (const ulonglong2*)(h2buf[s ^ 1] + half * 32);
#pragma unroll
            for (int k = 0; k < 4; ++k) {
                ulonglong2 g01 = gp[2 * k];
                ulonglong2 g23 = gp[2 * k + 1];
                fma2(a0, whp[4 * k + 0], g01.x);
                fma2(a1, whp[4 * k + 1], g01.y);
                fma2(a2, whp[4 * k + 2], g23.x);
                fma2(a3, whp[4 * k + 3], g23.y);
            }
            ull s01, s23, sall;
            add2(s01, a0, a1);
            add2(s23, a2, a3);
            add2(sall, s01, s23);
            float d = lo32(sall) + hi32(sall);

            BAR_ARRIVE(3 + s, 256);                    // EMPTY[s]: done reading h1buf[s]

            d += __shfl_xor_sync(0xffffffffu, d, 1);
            if (!half) h2buf[s][j] = fast_tanh(d + bias2);
            BAR_SYNC(6, 128);                          // L2 internal
        }

        // ---- FC head on warp 4: out[bb] = W_fc2 @ relu(W_fc1 @ h2(T-1) + b_fc1) + b_fc2
        // h2(T-1) lives in h2buf[(TSEQ-1)&1] == h2buf[1]; L2-internal barrier made it visible.
        if (u < F1) {
            const float* hf = h2buf[(TSEQ - 1) & 1];
            float acc = b_fc1[u];
#pragma unroll
            for (int k = 0; k < H2; ++k) acc = fmaf(W_fc1[u * H2 + k], hf[k], acc);
            float r = fmaxf(acc, 0.f) * W_fc2[u];
#pragma unroll
            for (int sft = 16; sft > 0; sft >>= 1) r += __shfl_xor_sync(0xffffffffu, r, sft);
            if (u == 0) out[bb] = r + b_fc2[0];
        }
    }
}

// =====================================================================================
extern "C" void kernel_launch(void* const* d_in, const int* in_sizes, int n_in,
                              void* d_out, int out_size)
{
    const float* x     = (const float*)d_in[0];
    const float* W_ih1 = (const float*)d_in[1];
    const float* W_hh1 = (const float*)d_in[2];
    const float* b_ih1 = (const float*)d_in[3];
    const float* b_hh1 = (const float*)d_in[4];
    const float* W_ih2 = (const float*)d_in[5];
    const float* W_hh2 = (const float*)d_in[6];
    const float* b_ih2 = (const float*)d_in[7];
    const float* b_hh2 = (const float*)d_in[8];
    const float* W_fc1 = (const float*)d_in[9];
    const float* b_fc1 = (const float*)d_in[10];
    const float* W_fc2 = (const float*)d_in[11];
    const float* b_fc2 = (const float*)d_in[12];
    float* out = (float*)d_out;

    gemm_xp1_kernel<<<MTOT / 128, 256>>>(x, W_ih1, b_ih1);
    rnn_scan_kernel<<<BATCH, 256>>>(W_hh1, b_hh1, W_ih2, W_hh2, b_ih2, b_hh2,
                                    W_fc1, b_fc1, W_fc2, b_fc2, out);
}

// round 6
// speedup vs baseline: 2.0128x; 1.2318x over previous
#include <cuda_runtime.h>
#include <cstdint>

#define D_IN  2048
#define H1    128
#define H2    64
#define F1    32
#define BATCH 64
#define TSEQ  512
#define MTOT  (BATCH * TSEQ)   // 32768

typedef unsigned long long ull;

// ---- static device scratch (allocation-free) ----
__device__ float g_xp1[MTOT * H1];                          // 16 MB
__device__ __align__(16) unsigned short g_whi[H1 * D_IN];   // W_ih1 bf16 hi
__device__ __align__(16) unsigned short g_wlo[H1 * D_IN];   // W_ih1 bf16 lo

// ---------------- packed f32x2 helpers (scan) ----------------
__device__ __forceinline__ void fma2(ull &acc, ull a, ull b) {
    asm("fma.rn.f32x2 %0, %1, %2, %0;" : "+l"(acc) : "l"(a), "l"(b));
}
__device__ __forceinline__ void add2(ull &d, ull a, ull b) {
    asm("add.rn.f32x2 %0, %1, %2;" : "=l"(d) : "l"(a), "l"(b));
}
__device__ __forceinline__ float lo32(ull v) { return __uint_as_float((unsigned)v); }
__device__ __forceinline__ float hi32(ull v) { return __uint_as_float((unsigned)(v >> 32)); }

__device__ __forceinline__ float fast_tanh(float x) {
    float e = __expf(2.0f * x);
    return 1.0f - __fdividef(2.0f, e + 1.0f);
}

#define BAR_SYNC(id, n)   asm volatile("bar.sync %0, %1;"   :: "r"(id), "r"(n) : "memory")
#define BAR_ARRIVE(id, n) asm volatile("bar.arrive %0, %1;" :: "r"(id), "r"(n) : "memory")

__device__ __forceinline__ uint32_t smem_u32(const void* p) {
    uint32_t a;
    asm("{ .reg .u64 t; cvta.to.shared.u64 t, %1; cvt.u32.u64 %0, t; }" : "=r"(a) : "l"(p));
    return a;
}

// ---------------- mma.sync / ldmatrix primitives (legal on compute_103) ----------------
__device__ __forceinline__ void mma_bf16(float4 &d, uint4 a, uint32_t b0, uint32_t b1) {
    asm volatile(
        "mma.sync.aligned.m16n8k16.row.col.f32.bf16.bf16.f32 "
        "{%0,%1,%2,%3}, {%4,%5,%6,%7}, {%8,%9}, {%0,%1,%2,%3};"
        : "+f"(d.x), "+f"(d.y), "+f"(d.z), "+f"(d.w)
        : "r"(a.x), "r"(a.y), "r"(a.z), "r"(a.w), "r"(b0), "r"(b1));
}
__device__ __forceinline__ uint4 ldsm4(uint32_t addr) {
    uint4 v;
    asm volatile("ldmatrix.sync.aligned.m8n8.x4.shared.b16 {%0,%1,%2,%3}, [%4];"
        : "=r"(v.x), "=r"(v.y), "=r"(v.z), "=r"(v.w) : "r"(addr));
    return v;
}

// split one fp32 float4 into hi/lo bf16x2 pairs
__device__ __forceinline__ void cvt_split(float4 v, uint2& hi, uint2& lo) {
    uint32_t h01, h23, l01, l23;
    asm("cvt.rn.bf16x2.f32 %0, %1, %2;" : "=r"(h01) : "f"(v.y), "f"(v.x));
    asm("cvt.rn.bf16x2.f32 %0, %1, %2;" : "=r"(h23) : "f"(v.w), "f"(v.z));
    float b0 = __uint_as_float(h01 << 16);
    float b1 = __uint_as_float(h01 & 0xffff0000u);
    float b2 = __uint_as_float(h23 << 16);
    float b3 = __uint_as_float(h23 & 0xffff0000u);
    asm("cvt.rn.bf16x2.f32 %0, %1, %2;" : "=r"(l01) : "f"(v.y - b1), "f"(v.x - b0));
    asm("cvt.rn.bf16x2.f32 %0, %1, %2;" : "=r"(l23) : "f"(v.w - b3), "f"(v.z - b2));
    hi = make_uint2(h01, h23);
    lo = make_uint2(l01, l23);
}

// =====================================================================================
// Kernel 0: pre-split W_ih1 (128x2048 fp32) into bf16 hi/lo globals. 65536 float4s.
// =====================================================================================
__global__ void __launch_bounds__(256, 1) convert_w_kernel(const float* __restrict__ W)
{
    int idx = blockIdx.x * 256 + threadIdx.x;        // grid 256 -> 65536 threads
    float4 v = ((const float4*)W)[idx];
    uint2 hi, lo;
    cvt_split(v, hi, lo);
    ((uint2*)g_whi)[idx] = hi;
    ((uint2*)g_wlo)[idx] = lo;
}

// =====================================================================================
// Kernel 1: xp1 = x @ W_ih1^T + b_ih1 via mma.sync bf16 3-term split.
// CTA tile 128x128, 64 k-stages of 32 fp32 cols. 256 thr = 8 warps (4x2 warp grid,
// warp tile 32x64). A converted in-kernel; B tiles read pre-split from g_whi/g_wlo.
// Smem rows at 80B pitch (r*80 mod 128 permutes 8 rows over 8 slots -> conflict-free).
// =====================================================================================
#define PITCH  80
#define NSTG   64                 // 2048 / 32
#define ATILE  (128 * PITCH)      // 10240 B per bf16 tile
#define BUFSZ  (4 * ATILE)        // A_hi, A_lo, B_hi, B_lo
#define GSMEM  (512 + 2 * BUFSZ)  // bias + double buffer = 82432 B

__device__ __forceinline__ void stage_store(char* buf, uint32_t off,
                                            const float4* ra, const uint4* rbh, const uint4* rbl)
{
    char* Ahi = buf;
    char* Alo = buf + ATILE;
    char* Bhi = buf + 2 * ATILE;
    char* Blo = buf + 3 * ATILE;
#pragma unroll
    for (int f = 0; f < 4; ++f) {
        uint2 hi, lo;
        cvt_split(ra[f], hi, lo);
        *(uint2*)(Ahi + off + f * 8) = hi;
        *(uint2*)(Alo + off + f * 8) = lo;
    }
    *(uint4*)(Bhi + off)      = rbh[0];
    *(uint4*)(Bhi + off + 16) = rbh[1];
    *(uint4*)(Blo + off)      = rbl[0];
    *(uint4*)(Blo + off + 16) = rbl[1];
}

__global__ void __launch_bounds__(256, 1) gemm_mma_kernel(
    const float* __restrict__ X, const float* __restrict__ bias)
{
    extern __shared__ __align__(16) char smem[];
    float* biasS = (float*)smem;
    char* bufb = smem + 512;
    const uint32_t sb = smem_u32(bufb);

    const int tid = threadIdx.x, lane = tid & 31, w = tid >> 5;
    const int wm = w & 3, wn = w >> 2;
    const int mBase = blockIdx.x * 128;

    if (tid < 128) biasS[tid] = bias[tid];

    // staging thread mapping: (row, half) each handle 16 fp32 cols per stage
    const int row = tid >> 1, half = tid & 1;
    const float* Arow = X + (size_t)(mBase + row) * D_IN + half * 16;
    const char* BhiG = (const char*)g_whi + (size_t)row * D_IN * 2 + half * 32;
    const char* BloG = (const char*)g_wlo + (size_t)row * D_IN * 2 + half * 32;
    const uint32_t sts_off = (uint32_t)(row * PITCH + half * 32);

    // ldmatrix lane offsets
    const uint32_t aoff = (uint32_t)((wm * 32 + (lane & 15)) * PITCH + (lane >> 4) * 16);
    const uint32_t boff = (uint32_t)((wn * 64 + (lane & 7) + ((lane >> 4) & 1) * 8) * PITCH
                                     + ((lane >> 3) & 1) * 16);

    float4 acc[2][8];
#pragma unroll
    for (int mi = 0; mi < 2; ++mi)
#pragma unroll
        for (int ni = 0; ni < 8; ++ni) acc[mi][ni] = make_float4(0.f, 0.f, 0.f, 0.f);

    float4 ra[4];
    uint4 rbh[2], rbl[2];
#pragma unroll
    for (int f = 0; f < 4; ++f) ra[f] = *(const float4*)(Arow + f * 4);
    rbh[0] = *(const uint4*)(BhiG);
    rbh[1] = *(const uint4*)(BhiG + 16);
    rbl[0] = *(const uint4*)(BloG);
    rbl[1] = *(const uint4*)(BloG + 16);
    stage_store(bufb, sts_off, ra, rbh, rbl);
    __syncthreads();

    for (int i = 0; i < NSTG; ++i) {
        const int cur = i & 1;
        if (i + 1 < NSTG) {                       // prefetch next stage into regs
            const int ko = (i + 1) * 32;
#pragma unroll
            for (int f = 0; f < 4; ++f) ra[f] = *(const float4*)(Arow + ko + f * 4);
            rbh[0] = *(const uint4*)(BhiG + ko * 2);
            rbh[1] = *(const uint4*)(BhiG + ko * 2 + 16);
            rbl[0] = *(const uint4*)(BloG + ko * 2);
            rbl[1] = *(const uint4*)(BloG + ko * 2 + 16);
        }

        const uint32_t Ahi = sb + cur * BUFSZ;
        const uint32_t Alo = Ahi + ATILE;
        const uint32_t Bhi = Ahi + 2 * ATILE;
        const uint32_t Blo = Ahi + 3 * ATILE;

#pragma unroll
        for (int kc = 0; kc < 2; ++kc) {          // two k16 chunks per stage
            const uint32_t kb = kc * 32;          // 16 bf16 = 32 B

            uint4 ah0 = ldsm4(Ahi + aoff + kb);
            uint4 ah1 = ldsm4(Ahi + aoff + 16 * PITCH + kb);
            uint4 bh0 = ldsm4(Bhi + boff + kb);
            uint4 bh1 = ldsm4(Bhi + boff + 16 * PITCH + kb);
            uint4 bh2 = ldsm4(Bhi + boff + 32 * PITCH + kb);
            uint4 bh3 = ldsm4(Bhi + boff + 48 * PITCH + kb);

            mma_bf16(acc[0][0], ah0, bh0.x, bh0.y);
            mma_bf16(acc[0][1], ah0, bh0.z, bh0.w);
            mma_bf16(acc[0][2], ah0, bh1.x, bh1.y);
            mma_bf16(acc[0][3], ah0, bh1.z, bh1.w);
            mma_bf16(acc[0][4], ah0, bh2.x, bh2.y);
            mma_bf16(acc[0][5], ah0, bh2.z, bh2.w);
            mma_bf16(acc[0][6], ah0, bh3.x, bh3.y);
            mma_bf16(acc[0][7], ah0, bh3.z, bh3.w);
            mma_bf16(acc[1][0], ah1, bh0.x, bh0.y);
            mma_bf16(acc[1][1], ah1, bh0.z, bh0.w);
            mma_bf16(acc[1][2], ah1, bh1.x, bh1.y);
            mma_bf16(acc[1][3], ah1, bh1.z, bh1.w);
            mma_bf16(acc[1][4], ah1, bh2.x, bh2.y);
            mma_bf16(acc[1][5], ah1, bh2.z, bh2.w);
            mma_bf16(acc[1][6], ah1, bh3.x, bh3.y);
            mma_bf16(acc[1][7], ah1, bh3.z, bh3.w);

            uint4 bl0 = ldsm4(Blo + boff + kb);
            uint4 bl1 = ldsm4(Blo + boff + 16 * PITCH + kb);
            uint4 bl2 = ldsm4(Blo + boff + 32 * PITCH + kb);
            uint4 bl3 = ldsm4(Blo + boff + 48 * PITCH + kb);

            mma_bf16(acc[0][0], ah0, bl0.x, bl0.y);
            mma_bf16(acc[0][1], ah0, bl0.z, bl0.w);
            mma_bf16(acc[0][2], ah0, bl1.x, bl1.y);
            mma_bf16(acc[0][3], ah0, bl1.z, bl1.w);
            mma_bf16(acc[0][4], ah0, bl2.x, bl2.y);
            mma_bf16(acc[0][5], ah0, bl2.z, bl2.w);
            mma_bf16(acc[0][6], ah0, bl3.x, bl3.y);
            mma_bf16(acc[0][7], ah0, bl3.z, bl3.w);
            mma_bf16(acc[1][0], ah1, bl0.x, bl0.y);
            mma_bf16(acc[1][1], ah1, bl0.z, bl0.w);
            mma_bf16(acc[1][2], ah1, bl1.x, bl1.y);
            mma_bf16(acc[1][3], ah1, bl1.z, bl1.w);
            mma_bf16(acc[1][4], ah1, bl2.x, bl2.y);
            mma_bf16(acc[1][5], ah1, bl2.z, bl2.w);
            mma_bf16(acc[1][6], ah1, bl3.x, bl3.y);
            mma_bf16(acc[1][7], ah1, bl3.z, bl3.w);

            uint4 al0 = ldsm4(Alo + aoff + kb);
            uint4 al1 = ldsm4(Alo + aoff + 16 * PITCH + kb);

            mma_bf16(acc[0][0], al0, bh0.x, bh0.y);
            mma_bf16(acc[0][1], al0, bh0.z, bh0.w);
            mma_bf16(acc[0][2], al0, bh1.x, bh1.y);
            mma_bf16(acc[0][3], al0, bh1.z, bh1.w);
            mma_bf16(acc[0][4], al0, bh2.x, bh2.y);
            mma_bf16(acc[0][5], al0, bh2.z, bh2.w);
            mma_bf16(acc[0][6], al0, bh3.x, bh3.y);
            mma_bf16(acc[0][7], al0, bh3.z, bh3.w);
            mma_bf16(acc[1][0], al1, bh0.x, bh0.y);
            mma_bf16(acc[1][1], al1, bh0.z, bh0.w);
            mma_bf16(acc[1][2], al1, bh1.x, bh1.y);
            mma_bf16(acc[1][3], al1, bh1.z, bh1.w);
            mma_bf16(acc[1][4], al1, bh2.x, bh2.y);
            mma_bf16(acc[1][5], al1, bh2.z, bh2.w);
            mma_bf16(acc[1][6], al1, bh3.x, bh3.y);
            mma_bf16(acc[1][7], al1, bh3.z, bh3.w);
        }

        if (i + 1 < NSTG) stage_store(bufb + (cur ^ 1) * BUFSZ, sts_off, ra, rbh, rbl);
        __syncthreads();
    }

    // ---------------- epilogue: add bias, store fp32 ----------------
    const int row0 = mBase + wm * 32 + (lane >> 2);
    const int cb = wn * 64 + (lane & 3) * 2;
#pragma unroll
    for (int mi = 0; mi < 2; ++mi)
#pragma unroll
        for (int ni = 0; ni < 8; ++ni) {
            const int r = row0 + mi * 16;
            const int c = cb + ni * 8;
            float2 v;
            v.x = acc[mi][ni].x + biasS[c];
            v.y = acc[mi][ni].y + biasS[c + 1];
            *(float2*)(g_xp1 + (size_t)r * H1 + c) = v;
            v.x = acc[mi][ni].z + biasS[c];
            v.y = acc[mi][ni].w + biasS[c + 1];
            *(float2*)(g_xp1 + (size_t)(r + 8) * H1 + c) = v;
        }
}

// =====================================================================================
// Kernel 2: warp-specialized dual-RNN scan + FC head. One CTA per batch, 256 threads.
// L1 (thr 0-127): per step = 1 bar.sync(EMPTY) + 1 bar.arrive(FULL).
// L2 (thr 128-255): 1 bar.sync(FULL) + 1 bar.arrive(EMPTY), register-staged early release.
// =====================================================================================
__global__ void __launch_bounds__(256, 1) rnn_scan_kernel(
    const float* __restrict__ W_hh1, const float* __restrict__ b_hh1,
    const float* __restrict__ W_ih2, const float* __restrict__ W_hh2,
    const float* __restrict__ b_ih2, const float* __restrict__ b_hh2,
    const float* __restrict__ W_fc1, const float* __restrict__ b_fc1,
    const float* __restrict__ W_fc2, const float* __restrict__ b_fc2,
    float* __restrict__ out)
{
    __shared__ __align__(16) float h1buf[2][H1];
    __shared__ __align__(16) float h2buf[2][H2];

    const int tid = threadIdx.x;
    const int bb = blockIdx.x;

    if (tid < H1) h1buf[1][tid] = 0.f;   // h1(-1), read at t=0
    if (tid < H2) h2buf[1][tid] = 0.f;   // h2(-1)
    __syncthreads();

    if (tid < 128) {
        // ---------------- LAYER 1 ----------------
        const int i = tid;
        ull w1p[64];
#pragma unroll
        for (int k = 0; k < 64; ++k)
            w1p[k] = *(const ull*)(W_hh1 + i * H1 + 2 * k);
        const float bias = b_hh1[i];

        const float* xp = g_xp1 + (size_t)bb * TSEQ * H1;
        float xv = __ldg(xp + i);

        for (int t = 0; t < TSEQ; ++t) {
            const int s = t & 1;
            BAR_SYNC(3 + s, 256);        // EMPTY[s] (pre-armed by L2 for t=0,1)

            float xnext = 0.f;
            if (t < TSEQ - 1) xnext = __ldg(xp + (t + 1) * H1 + i);

            const ulonglong2* hp = (const ulonglong2*)h1buf[s ^ 1];
            ull a0 = 0, a1 = 0, a2 = 0, a3 = 0;
#pragma unroll
            for (int k = 0; k < 16; ++k) {
                ulonglong2 h01 = hp[2 * k];
                ulonglong2 h23 = hp[2 * k + 1];
                fma2(a0, w1p[4 * k + 0], h01.x);
                fma2(a1, w1p[4 * k + 1], h01.y);
                fma2(a2, w1p[4 * k + 2], h23.x);
                fma2(a3, w1p[4 * k + 3], h23.y);
            }
            ull s01, s23, sall;
            add2(s01, a0, a1);
            add2(s23, a2, a3);
            add2(sall, s01, s23);
            float dot = lo32(sall) + hi32(sall);

            h1buf[s][i] = fast_tanh(xv + bias + dot);
            BAR_ARRIVE(1 + s, 256);      // FULL[s]
            xv = xnext;
        }
    } else {
        // ---------------- LAYER 2 ----------------
        const int u = tid - 128;
        const int j = u >> 1, half = u & 1;

        BAR_ARRIVE(3, 256);              // pre-arm EMPTY[0]
        BAR_ARRIVE(4, 256);              // pre-arm EMPTY[1]

        ull wip[32];                     // W_ih2[j, half*64 .. +64) as 32 packed pairs
#pragma unroll
        for (int k = 0; k < 32; ++k)
            wip[k] = *(const ull*)(W_ih2 + j * H1 + half * 64 + 2 * k);
        ull whp[16];                     // W_hh2[j, half*32 .. +32) as 16 packed pairs
#pragma unroll
        for (int k = 0; k < 16; ++k)
            whp[k] = *(const ull*)(W_hh2 + j * H2 + half * 32 + 2 * k);
        const float bias2 = b_ih2[j] + b_hh2[j];

        for (int t = 0; t < TSEQ; ++t) {
            const int s = t & 1;
            BAR_SYNC(1 + s, 256);        // FULL[s]: h1(t) ready (also fences our h2 writes)

            // stage h1 slice into regs, release the buffer ASAP
            ulonglong2 hv[16];           // 64 floats
            const ulonglong2* hp = (const ulonglong2*)(h1buf[s] + half * 64);
#pragma unroll
            for (int k = 0; k < 16; ++k) hv[k] = hp[k];
            BAR_ARRIVE(3 + s, 256);      // EMPTY[s]

            ull a0 = 0, a1 = 0, a2 = 0, a3 = 0;
#pragma unroll
            for (int k = 0; k < 8; ++k) {
                fma2(a0, wip[4 * k + 0], hv[2 * k].x);
                fma2(a1, wip[4 * k + 1], hv[2 * k].y);
                fma2(a2, wip[4 * k + 2], hv[2 * k + 1].x);
                fma2(a3, wip[4 * k + 3], hv[2 * k + 1].y);
            }
            const ulonglong2* gp = (const ulonglong2*)(h2buf[s ^ 1] + half * 32);
#pragma unroll
            for (int k = 0; k < 4; ++k) {
                ulonglong2 g01 = gp[2 * k];
                ulonglong2 g23 = gp[2 * k + 1];
                fma2(a0, whp[4 * k + 0], g01.x);
                fma2(a1, whp[4 * k + 1], g01.y);
                fma2(a2, whp[4 * k + 2], g23.x);
                fma2(a3, whp[4 * k + 3], g23.y);
            }
            ull s01, s23, sall;
            add2(s01, a0, a1);
            add2(s23, a2, a3);
            add2(sall, s01, s23);
            float d = lo32(sall) + hi32(sall);

            d += __shfl_xor_sync(0xffffffffu, d, 1);
            if (!half) h2buf[s][j] = fast_tanh(d + bias2);
        }

        BAR_SYNC(6, 128);                // L2-internal: final h2 visible for FC

        if (u < F1) {
            const float* hf = h2buf[(TSEQ - 1) & 1];
            float acc = b_fc1[u];
#pragma unroll
            for (int k = 0; k < H2; ++k) acc = fmaf(W_fc1[u * H2 + k], hf[k], acc);
            float r = fmaxf(acc, 0.f) * W_fc2[u];
#pragma unroll
            for (int sft = 16; sft > 0; sft >>= 1) r += __shfl_xor_sync(0xffffffffu, r, sft);
            if (u == 0) out[bb] = r + b_fc2[0];
        }
    }
}

// =====================================================================================
extern "C" void kernel_launch(void* const* d_in, const int* in_sizes, int n_in,
                              void* d_out, int out_size)
{
    const float* x     = (const float*)d_in[0];
    const float* W_ih1 = (const float*)d_in[1];
    const float* W_hh1 = (const float*)d_in[2];
    const float* b_ih1 = (const float*)d_in[3];
    const float* b_hh1 = (const float*)d_in[4];
    const float* W_ih2 = (const float*)d_in[5];
    const float* W_hh2 = (const float*)d_in[6];
    const float* b_ih2 = (const float*)d_in[7];
    const float* b_hh2 = (const float*)d_in[8];
    const float* W_fc1 = (const float*)d_in[9];
    const float* b_fc1 = (const float*)d_in[10];
    const float* W_fc2 = (const float*)d_in[11];
    const float* b_fc2 = (const float*)d_in[12];
    float* out = (float*)d_out;

    convert_w_kernel<<<256, 256>>>(W_ih1);
    cudaFuncSetAttribute(gemm_mma_kernel, cudaFuncAttributeMaxDynamicSharedMemorySize, GSMEM);
    gemm_mma_kernel<<<MTOT / 128, 256, GSMEM>>>(x, b_ih1);
    rnn_scan_kernel<<<BATCH, 256>>>(W_hh1, b_hh1, W_ih2, W_hh2, b_ih2, b_hh2,
                                    W_fc1, b_fc1, W_fc2, b_fc2, out);
}